// round 1
// baseline (speedup 1.0000x reference)
#include <cuda_runtime.h>
#include <math.h>
#include <stdint.h>

#define S_ 4
#define K_ 50
#define T_ 25
#define R_ 128
#define V_ 10000
#define TH_ 800
#define EH_ 200
#define B_ 128
#define VK_ (V_ + K_)
#define LOG_DELTA (-5.2983173665480363f) /* log(0.005) */

// ---------------- scratch (static device globals; no allocation) -------------
__device__ float g_xemb[T_ * EH_];
__device__ float g_etas[T_ * K_];
__device__ float g_A1[B_ * VK_];
__device__ float g_h1[B_ * TH_];
__device__ float g_h2[B_ * TH_];
__device__ float g_muth[B_ * K_];
__device__ float g_lsth[B_ * K_];
__device__ float g_theta[B_ * K_];
__device__ float g_alpha0[T_ * K_ * R_];
__device__ float g_beta[(size_t)T_ * K_ * V_];   // 12.5M floats = 50 MB
// stats: 0=kl_alpha 1=kl_eta 2=nll_raw 3=klth_raw 4=ld_p0 5..8=d_p0 9=ld_pt 10..13=d_pt
__device__ float g_stats[16];

// ---------------- helpers ----------------------------------------------------
__device__ __forceinline__ float sigmoidf_(float x) { return 1.0f / (1.0f + expf(-x)); }

__device__ __forceinline__ float blockReduceSum256(float v, float* sh) {
    int tid = threadIdx.x;
    sh[tid] = v;
    __syncthreads();
    for (int s = blockDim.x >> 1; s > 0; s >>= 1) {
        if (tid < s) sh[tid] += sh[tid + s];
        __syncthreads();
    }
    return sh[0];
}

__device__ double logabsdet4(double M[4][4]) {
    double ld = 0.0;
    for (int i = 0; i < 4; i++) {
        int p = i; double best = fabs(M[i][i]);
        for (int r = i + 1; r < 4; r++)
            if (fabs(M[r][i]) > best) { best = fabs(M[r][i]); p = r; }
        if (p != i)
            for (int c = 0; c < 4; c++) { double t = M[i][c]; M[i][c] = M[p][c]; M[p][c] = t; }
        ld += log(fabs(M[i][i]));
        for (int r = i + 1; r < 4; r++) {
            double f = M[r][i] / M[i][i];
            for (int c = i; c < 4; c++) M[r][c] -= f * M[i][c];
        }
    }
    return ld;
}

// ---------------- kernels ----------------------------------------------------
__global__ void init_kernel() {
    int t = threadIdx.x;
    if (t < 16) g_stats[t] = 0.0f;
}

__global__ void prep_prior_kernel(const float* __restrict__ src) {
    // single thread: 4x4 slogdets + diagonals
    double M0[4][4], Mt[4][4];
    for (int i = 0; i < 4; i++)
        for (int j = 0; j < 4; j++) {
            double v = (double)src[i * 4 + j];
            M0[i][j] = exp(v);
            Mt[i][j] = 0.005 * v;
        }
    for (int i = 0; i < 4; i++) {
        g_stats[5 + i]  = (float)M0[i][i];
        g_stats[10 + i] = (float)Mt[i][i];
    }
    g_stats[4] = (float)logabsdet4(M0);
    g_stats[9] = (float)logabsdet4(Mt);
}

__global__ void kl_alpha_kernel(const float* __restrict__ mu, const float* __restrict__ lsig) {
    __shared__ float sh[256];
    int idx = blockIdx.x * blockDim.x + threadIdx.x;
    float val = 0.0f;
    if (idx < K_ * T_ * R_) {
        int r = idx % R_;
        int t = (idx / R_) % T_;
        int k = idx / (R_ * T_);
        float ldp = (t == 0) ? g_stats[4] : g_stats[9];
        const float* dp = (t == 0) ? &g_stats[5] : &g_stats[10];
        float acc = -ldp - (float)S_;
        for (int s = 0; s < S_; s++) {
            size_t off = ((size_t)(s * K_ + k) * T_ + t) * R_ + r;
            float lsv = lsig[off];
            float invq = expf(-lsv);
            float m = mu[off];
            float dmu = (t == 0) ? m : (m - mu[off - R_]);
            acc += lsv + dp[s] * invq + dmu * dmu * invq;
        }
        val = acc;
    }
    float tot = blockReduceSum256(val, sh);
    if (threadIdx.x == 0) atomicAdd(&g_stats[0], tot);
}

// x_emb[t][e] = rnn_inp[t] . eta_map_W[e] + b[e]   (warp per output)
__global__ void xemb_kernel(const float* __restrict__ rnn, const float* __restrict__ W,
                            const float* __restrict__ b) {
    int gw = (blockIdx.x * blockDim.x + threadIdx.x) >> 5;
    int lane = threadIdx.x & 31;
    if (gw >= T_ * EH_) return;
    int t = gw / EH_, e = gw % EH_;
    const float* x = rnn + (size_t)t * V_;
    const float* w = W + (size_t)e * V_;
    float acc = 0.0f;
    for (int v = lane; v < V_; v += 32) acc += x[v] * w[v];
    for (int o = 16; o > 0; o >>= 1) acc += __shfl_down_sync(0xffffffffu, acc, o);
    if (lane == 0) g_xemb[t * EH_ + e] = acc + b[e];
}

// sequential LSTM (T=25) + eta Markov scan, single block of 800 threads
__global__ void lstm_eta_kernel(const float* __restrict__ Wih, const float* __restrict__ Whh,
                                const float* __restrict__ bih, const float* __restrict__ bhh,
                                const float* __restrict__ muW, const float* __restrict__ mub,
                                const float* __restrict__ lsW, const float* __restrict__ lsb) {
    __shared__ float xs[EH_], hs[EH_], cs[EH_], gs[4 * EH_];
    __shared__ float inp[EH_ + K_], newmu[K_], klk[K_];
    int tid = threadIdx.x;
    if (tid < EH_) { hs[tid] = 0.0f; cs[tid] = 0.0f; inp[tid] = 0.0f; }
    if (tid < K_) inp[EH_ + tid] = 0.0f;
    __syncthreads();
    float klacc = 0.0f;
    for (int t = 0; t < T_; t++) {
        if (tid < EH_) xs[tid] = g_xemb[t * EH_ + tid];
        __syncthreads();
        {
            const float* wi = Wih + (size_t)tid * EH_;
            const float* wh = Whh + (size_t)tid * EH_;
            float a = bih[tid] + bhh[tid];
            #pragma unroll 4
            for (int i = 0; i < EH_; i++) a += xs[i] * wi[i] + hs[i] * wh[i];
            gs[tid] = a;
        }
        __syncthreads();
        if (tid < EH_) {
            float ig = sigmoidf_(gs[tid]);
            float fg = sigmoidf_(gs[EH_ + tid]);
            float gg = tanhf(gs[2 * EH_ + tid]);
            float og = sigmoidf_(gs[3 * EH_ + tid]);
            float c = fg * cs[tid] + ig * gg;
            cs[tid] = c;
            float h = og * tanhf(c);
            hs[tid] = h;
            inp[tid] = h;
        }
        __syncthreads();
        if (tid < K_) {
            const float* wm = muW + tid * (EH_ + K_);
            const float* wl = lsW + tid * (EH_ + K_);
            float m = mub[tid], l = lsb[tid];
            #pragma unroll 5
            for (int i = 0; i < EH_ + K_; i++) { float x = inp[i]; m += wm[i] * x; l += wl[i] * x; }
            float pls = (t == 0) ? 0.0f : LOG_DELTA;
            float denom = expf(pls) + 1e-6f;
            float ep = inp[EH_ + tid];
            float d = m - ep;
            klk[tid] = 0.5f * ((expf(l) + d * d) / denom - 1.0f + pls - l);
            newmu[tid] = m;
            g_etas[t * K_ + tid] = m;
        }
        __syncthreads();
        if (tid < K_) inp[EH_ + tid] = newmu[tid];
        if (tid == 0) { float s = 0.0f; for (int k = 0; k < K_; k++) s += klk[k]; klacc += s; }
        __syncthreads();
    }
    if (tid == 0) g_stats[1] = klacc;
}

__global__ void build_A1_kernel(const float* __restrict__ nb, const int* __restrict__ times) {
    int idx = blockIdx.x * blockDim.x + threadIdx.x;
    if (idx >= B_ * VK_) return;
    int b = idx / VK_, j = idx % VK_;
    g_A1[idx] = (j < V_) ? nb[(size_t)b * V_ + j] : g_etas[times[b] * K_ + (j - V_)];
}

__global__ void build_alpha0_kernel(const float* __restrict__ mu) {
    int idx = blockIdx.x * blockDim.x + threadIdx.x;
    if (idx >= T_ * K_ * R_) return;
    int r = idx % R_;
    int k = (idx / R_) % K_;
    int t = idx / (R_ * K_);
    g_alpha0[idx] = mu[((size_t)k * T_ + t) * R_ + r];  // s=0 slice
}

// C[M,N] = act(A[M,Kd] * B[N,Kd]^T + bias)
template <int BM, int BN, int BK, int TM, int TN>
__global__ void sgemm_tn(const float* __restrict__ A, const float* __restrict__ Bm,
                         const float* __restrict__ bias, float* __restrict__ C,
                         int M, int N, int Kd, int act) {
    constexpr int TX = BN / TN;
    constexpr int TY = BM / TM;
    constexpr int NT = TX * TY;
    __shared__ float As[BK][BM + 1];
    __shared__ float Bs[BK][BN + 1];
    int tid = threadIdx.x;
    int tx = tid % TX, ty = tid / TX;
    int row0 = blockIdx.y * BM, col0 = blockIdx.x * BN;
    float acc[TM][TN];
    #pragma unroll
    for (int i = 0; i < TM; i++)
        #pragma unroll
        for (int j = 0; j < TN; j++) acc[i][j] = 0.0f;
    for (int k0 = 0; k0 < Kd; k0 += BK) {
        for (int i = tid; i < BM * BK; i += NT) {
            int m = i / BK, kk = i % BK;
            int gm = row0 + m, gk = k0 + kk;
            As[kk][m] = (gm < M && gk < Kd) ? A[(size_t)gm * Kd + gk] : 0.0f;
        }
        for (int i = tid; i < BN * BK; i += NT) {
            int n = i / BK, kk = i % BK;
            int gn = col0 + n, gk = k0 + kk;
            Bs[kk][n] = (gn < N && gk < Kd) ? Bm[(size_t)gn * Kd + gk] : 0.0f;
        }
        __syncthreads();
        #pragma unroll
        for (int kk = 0; kk < BK; kk++) {
            float a[TM], bb[TN];
            #pragma unroll
            for (int i = 0; i < TM; i++) a[i] = As[kk][ty * TM + i];
            #pragma unroll
            for (int j = 0; j < TN; j++) bb[j] = Bs[kk][tx * TN + j];
            #pragma unroll
            for (int i = 0; i < TM; i++)
                #pragma unroll
                for (int j = 0; j < TN; j++) acc[i][j] += a[i] * bb[j];
        }
        __syncthreads();
    }
    #pragma unroll
    for (int i = 0; i < TM; i++)
        #pragma unroll
        for (int j = 0; j < TN; j++) {
            int m = row0 + ty * TM + i, n = col0 + tx * TN + j;
            if (m < M && n < N) {
                float v = acc[i][j] + (bias ? bias[n] : 0.0f);
                if (act == 1) v = tanhf(v);
                C[(size_t)m * N + n] = v;
            }
        }
}

__global__ void softmax_beta_kernel() {
    __shared__ float red[256];
    int row = blockIdx.x, tid = threadIdx.x;
    float* p = g_beta + (size_t)row * V_;
    float mx = -1e30f;
    for (int v = tid; v < V_; v += 256) mx = fmaxf(mx, p[v]);
    red[tid] = mx; __syncthreads();
    for (int s = 128; s > 0; s >>= 1) { if (tid < s) red[tid] = fmaxf(red[tid], red[tid + s]); __syncthreads(); }
    mx = red[0]; __syncthreads();
    float sum = 0.0f;
    for (int v = tid; v < V_; v += 256) sum += expf(p[v] - mx);
    red[tid] = sum; __syncthreads();
    for (int s = 128; s > 0; s >>= 1) { if (tid < s) red[tid] += red[tid + s]; __syncthreads(); }
    float inv = 1.0f / red[0];
    for (int v = tid; v < V_; v += 256) p[v] = expf(p[v] - mx) * inv;
}

__global__ void theta_kl_kernel(const int* __restrict__ times) {
    __shared__ float red[64];
    int b = blockIdx.x, tid = threadIdx.x;  // 64 threads
    float mu = (tid < K_) ? g_muth[b * K_ + tid] : -1e30f;
    red[tid] = mu; __syncthreads();
    for (int s = 32; s > 0; s >>= 1) { if (tid < s) red[tid] = fmaxf(red[tid], red[tid + s]); __syncthreads(); }
    float mx = red[0]; __syncthreads();
    float e = (tid < K_) ? expf(mu - mx) : 0.0f;
    red[tid] = e; __syncthreads();
    for (int s = 32; s > 0; s >>= 1) { if (tid < s) red[tid] += red[tid + s]; __syncthreads(); }
    float sum = red[0]; __syncthreads();
    if (tid < K_) g_theta[b * K_ + tid] = e / sum;
    float kl = 0.0f;
    if (tid < K_) {
        float ls = g_lsth[b * K_ + tid];
        float et = g_etas[times[b] * K_ + tid];
        float d = mu - et;
        kl = 0.5f * ((expf(ls) + d * d) / (1.0f + 1e-6f) - 1.0f - ls);
    }
    red[tid] = kl; __syncthreads();
    for (int s = 32; s > 0; s >>= 1) { if (tid < s) red[tid] += red[tid + s]; __syncthreads(); }
    if (tid == 0) atomicAdd(&g_stats[3], red[0]);
}

__global__ void nll_kernel(const float* __restrict__ bows, const int* __restrict__ times) {
    __shared__ float th[K_];
    __shared__ float sh[256];
    int b = blockIdx.x, tid = threadIdx.x;
    if (tid < K_) th[tid] = g_theta[b * K_ + tid];
    __syncthreads();
    int tb = times[b];
    const float* beta = g_beta + (size_t)tb * K_ * V_;
    float acc = 0.0f;
    for (int v = tid; v < V_; v += 256) {
        float mix = 1e-6f;
        #pragma unroll 5
        for (int k = 0; k < K_; k++) mix += th[k] * beta[(size_t)k * V_ + v];
        acc -= logf(mix) * bows[(size_t)b * V_ + v];
    }
    float tot = blockReduceSum256(acc, sh);
    if (tid == 0) atomicAdd(&g_stats[2], tot);
}

__global__ void finalize_kernel(const int* __restrict__ num_docs, float* __restrict__ out,
                                int out_size) {
    float coeff = (float)num_docs[0] / (float)B_;
    float nll_s = g_stats[2] * coeff;
    float klth = g_stats[3] * coeff;
    float nelbo = nll_s + g_stats[0] + g_stats[1] + klth;
    if (out_size > 0) out[0] = nelbo;
    if (out_size > 1) out[1] = nll_s;
    if (out_size > 2) out[2] = g_stats[0];
    if (out_size > 3) out[3] = g_stats[1];
    if (out_size > 4) out[4] = klth;
}

// ---------------- launch ------------------------------------------------------
extern "C" void kernel_launch(void* const* d_in, const int* in_sizes, int n_in,
                              void* d_out, int out_size) {
    const float* mu_q_alpha   = (const float*)d_in[0];
    const float* lsig_q_alpha = (const float*)d_in[1];
    const float* src_logcov   = (const float*)d_in[2];
    const float* rho_W        = (const float*)d_in[3];
    const float* theta_W1     = (const float*)d_in[4];
    const float* theta_b1     = (const float*)d_in[5];
    const float* theta_W2     = (const float*)d_in[6];
    const float* theta_b2     = (const float*)d_in[7];
    const float* mu_theta_W   = (const float*)d_in[8];
    const float* mu_theta_b   = (const float*)d_in[9];
    const float* ls_theta_W   = (const float*)d_in[10];
    const float* ls_theta_b   = (const float*)d_in[11];
    const float* eta_map_W    = (const float*)d_in[12];
    const float* eta_map_b    = (const float*)d_in[13];
    const float* lstm_Wih     = (const float*)d_in[14];
    const float* lstm_Whh     = (const float*)d_in[15];
    const float* lstm_bih     = (const float*)d_in[16];
    const float* lstm_bhh     = (const float*)d_in[17];
    const float* mu_eta_W     = (const float*)d_in[18];
    const float* mu_eta_b     = (const float*)d_in[19];
    const float* ls_eta_W     = (const float*)d_in[20];
    const float* ls_eta_b     = (const float*)d_in[21];
    const float* bows         = (const float*)d_in[22];
    const float* norm_bows    = (const float*)d_in[23];
    const float* rnn_inp      = (const float*)d_in[24];
    const int*   times        = (const int*)d_in[25];
    const int*   num_docs     = (const int*)d_in[26];
    float* out = (float*)d_out;

    float *d_A1, *d_h1, *d_h2, *d_muth, *d_lsth, *d_alpha0, *d_beta;
    cudaGetSymbolAddress((void**)&d_A1, g_A1);
    cudaGetSymbolAddress((void**)&d_h1, g_h1);
    cudaGetSymbolAddress((void**)&d_h2, g_h2);
    cudaGetSymbolAddress((void**)&d_muth, g_muth);
    cudaGetSymbolAddress((void**)&d_lsth, g_lsth);
    cudaGetSymbolAddress((void**)&d_alpha0, g_alpha0);
    cudaGetSymbolAddress((void**)&d_beta, g_beta);

    init_kernel<<<1, 32>>>();
    prep_prior_kernel<<<1, 1>>>(src_logcov);
    {
        int n = K_ * T_ * R_;
        kl_alpha_kernel<<<(n + 255) / 256, 256>>>(mu_q_alpha, lsig_q_alpha);
    }
    {
        int warps = T_ * EH_;
        xemb_kernel<<<(warps * 32 + 255) / 256, 256>>>(rnn_inp, eta_map_W, eta_map_b);
    }
    lstm_eta_kernel<<<1, 4 * EH_>>>(lstm_Wih, lstm_Whh, lstm_bih, lstm_bhh,
                                    mu_eta_W, mu_eta_b, ls_eta_W, ls_eta_b);
    {
        int n = B_ * VK_;
        build_A1_kernel<<<(n + 255) / 256, 256>>>(norm_bows, times);
    }
    // h1 = tanh(A1 @ W1^T + b1)  : (128 x 10050) x (800 x 10050)^T
    {
        dim3 grid((TH_ + 31) / 32, (B_ + 31) / 32);
        sgemm_tn<32, 32, 32, 2, 2><<<grid, 256>>>(d_A1, theta_W1, theta_b1, d_h1,
                                                  B_, TH_, VK_, 1);
    }
    // h2 = tanh(h1 @ W2^T + b2)
    {
        dim3 grid((TH_ + 31) / 32, (B_ + 31) / 32);
        sgemm_tn<32, 32, 32, 2, 2><<<grid, 256>>>(d_h1, theta_W2, theta_b2, d_h2,
                                                  B_, TH_, TH_, 1);
    }
    // mu_th / ls_th
    {
        dim3 grid((K_ + 31) / 32, (B_ + 31) / 32);
        sgemm_tn<32, 32, 32, 2, 2><<<grid, 256>>>(d_h2, mu_theta_W, mu_theta_b, d_muth,
                                                  B_, K_, TH_, 0);
        sgemm_tn<32, 32, 32, 2, 2><<<grid, 256>>>(d_h2, ls_theta_W, ls_theta_b, d_lsth,
                                                  B_, K_, TH_, 0);
    }
    {
        int n = T_ * K_ * R_;
        build_alpha0_kernel<<<(n + 255) / 256, 256>>>(mu_q_alpha);
    }
    // beta logits: (1250 x 128) x (10000 x 128)^T
    {
        dim3 grid((V_ + 63) / 64, (T_ * K_ + 63) / 64);
        sgemm_tn<64, 64, 16, 4, 4><<<grid, 256>>>(d_alpha0, rho_W, nullptr, d_beta,
                                                  T_ * K_, V_, R_, 0);
    }
    softmax_beta_kernel<<<T_ * K_, 256>>>();
    theta_kl_kernel<<<B_, 64>>>(times);
    nll_kernel<<<B_, 256>>>(bows, times);
    finalize_kernel<<<1, 1>>>(num_docs, out, out_size);
}

// round 3
// speedup vs baseline: 2.2520x; 2.2520x over previous
#include <cuda_runtime.h>
#include <math.h>
#include <stdint.h>

#define S_ 4
#define K_ 50
#define T_ 25
#define R_ 128
#define V_ 10000
#define TH_ 800
#define EH_ 200
#define B_ 128
#define VK_ (V_ + K_)
#define GATE_ (4 * EH_)    /* 800 */
#define INP_  (EH_ + K_)   /* 250 */
#define LOG_DELTA (-5.2983173665480363f) /* log(0.005) */

// ---------------- scratch (static device globals; no allocation) -------------
__device__ float g_xemb[T_ * EH_];
__device__ float g_etas[T_ * K_];
__device__ float g_A1[B_ * VK_];
__device__ float g_h1[B_ * TH_];
__device__ float g_h2[B_ * TH_];
__device__ float g_muth[B_ * K_];
__device__ float g_lsth[B_ * K_];
__device__ float g_theta[B_ * K_];
__device__ float g_alpha0[T_ * K_ * R_];
__device__ float g_beta[(size_t)T_ * K_ * V_];   // 12.5M floats = 50 MB
// LSTM prep scratch
__device__ float g_WhhT[EH_ * GATE_];   // [200][800]
__device__ float g_muWT[INP_ * K_];     // [250][50]
__device__ float g_lsWT[INP_ * K_];
__device__ float g_biasc[GATE_];
__device__ float g_Gx[T_ * GATE_];      // x-part of gates, all t
// stats: 0=kl_alpha 1=kl_eta 2=nll_raw 3=klth_raw 4=ld_p0 5..8=d_p0 9=ld_pt 10..13=d_pt
__device__ float g_stats[16];

// ---------------- helpers ----------------------------------------------------
__device__ __forceinline__ float sigmoidf_(float x) { return 1.0f / (1.0f + expf(-x)); }

__device__ __forceinline__ float blockReduceSum256(float v, float* sh) {
    int tid = threadIdx.x;
    sh[tid] = v;
    __syncthreads();
    for (int s = blockDim.x >> 1; s > 0; s >>= 1) {
        if (tid < s) sh[tid] += sh[tid + s];
        __syncthreads();
    }
    return sh[0];
}

__device__ double logabsdet4(double M[4][4]) {
    double ld = 0.0;
    for (int i = 0; i < 4; i++) {
        int p = i; double best = fabs(M[i][i]);
        for (int r = i + 1; r < 4; r++)
            if (fabs(M[r][i]) > best) { best = fabs(M[r][i]); p = r; }
        if (p != i)
            for (int c = 0; c < 4; c++) { double t = M[i][c]; M[i][c] = M[p][c]; M[p][c] = t; }
        ld += log(fabs(M[i][i]));
        for (int r = i + 1; r < 4; r++) {
            double f = M[r][i] / M[i][i];
            for (int c = i; c < 4; c++) M[r][c] -= f * M[i][c];
        }
    }
    return ld;
}

// ---------------- kernels ----------------------------------------------------
__global__ void init_kernel() {
    int t = threadIdx.x;
    if (t < 16) g_stats[t] = 0.0f;
}

__global__ void prep_prior_kernel(const float* __restrict__ src) {
    double M0[4][4], Mt[4][4];
    for (int i = 0; i < 4; i++)
        for (int j = 0; j < 4; j++) {
            double v = (double)src[i * 4 + j];
            M0[i][j] = exp(v);
            Mt[i][j] = 0.005 * v;
        }
    for (int i = 0; i < 4; i++) {
        g_stats[5 + i]  = (float)M0[i][i];
        g_stats[10 + i] = (float)Mt[i][i];
    }
    g_stats[4] = (float)logabsdet4(M0);
    g_stats[9] = (float)logabsdet4(Mt);
}

// transpose LSTM/eta weights for coalesced sequential access + combined bias
__global__ void prep_lstm_kernel(const float* __restrict__ Whh,
                                 const float* __restrict__ muW, const float* __restrict__ lsW,
                                 const float* __restrict__ bih, const float* __restrict__ bhh) {
    int idx = blockIdx.x * blockDim.x + threadIdx.x;
    if (idx < GATE_ * EH_) {
        int o = idx / EH_, i = idx % EH_;
        g_WhhT[i * GATE_ + o] = Whh[idx];
    }
    if (idx < K_ * INP_) {
        int k = idx / INP_, i = idx % INP_;
        g_muWT[i * K_ + k] = muW[idx];
        g_lsWT[i * K_ + k] = lsW[idx];
    }
    if (idx < GATE_) g_biasc[idx] = bih[idx] + bhh[idx];
}

__global__ void kl_alpha_kernel(const float* __restrict__ mu, const float* __restrict__ lsig) {
    __shared__ float sh[256];
    int idx = blockIdx.x * blockDim.x + threadIdx.x;
    float val = 0.0f;
    if (idx < K_ * T_ * R_) {
        int r = idx % R_;
        int t = (idx / R_) % T_;
        int k = idx / (R_ * T_);
        float ldp = (t == 0) ? g_stats[4] : g_stats[9];
        const float* dp = (t == 0) ? &g_stats[5] : &g_stats[10];
        float acc = -ldp - (float)S_;
        for (int s = 0; s < S_; s++) {
            size_t off = ((size_t)(s * K_ + k) * T_ + t) * R_ + r;
            float lsv = lsig[off];
            float invq = expf(-lsv);
            float m = mu[off];
            float dmu = (t == 0) ? m : (m - mu[off - R_]);
            acc += lsv + dp[s] * invq + dmu * dmu * invq;
        }
        val = acc;
    }
    float tot = blockReduceSum256(val, sh);
    if (threadIdx.x == 0) atomicAdd(&g_stats[0], tot);
}

// x_emb[t][e] = rnn_inp[t] . eta_map_W[e] + b[e]   (warp per output, float4)
__global__ void xemb_kernel(const float* __restrict__ rnn, const float* __restrict__ W,
                            const float* __restrict__ b) {
    int gw = (blockIdx.x * blockDim.x + threadIdx.x) >> 5;
    int lane = threadIdx.x & 31;
    if (gw >= T_ * EH_) return;
    int t = gw / EH_, e = gw % EH_;
    const float4* x = (const float4*)(rnn + (size_t)t * V_);
    const float4* w = (const float4*)(W + (size_t)e * V_);
    float acc = 0.0f;
    for (int v = lane; v < V_ / 4; v += 32) {
        float4 a = x[v], c = w[v];
        acc += a.x * c.x + a.y * c.y + a.z * c.z + a.w * c.w;
    }
    for (int o = 16; o > 0; o >>= 1) acc += __shfl_down_sync(0xffffffffu, acc, o);
    if (lane == 0) g_xemb[t * EH_ + e] = acc + b[e];
}

// sequential LSTM recurrence + eta Markov scan; x-part of gates precomputed (g_Gx).
// Coalesced weight reads through transposed copies. Single block, 800 threads.
__global__ void lstm_eta_kernel(const float* __restrict__ mub, const float* __restrict__ lsb) {
    __shared__ float hs[EH_], gs[GATE_];
    __shared__ float inp[INP_], newmu[K_], klk[K_];
    __shared__ float csv[EH_];
    int tid = threadIdx.x;
    if (tid < EH_) { hs[tid] = 0.0f; csv[tid] = 0.0f; inp[tid] = 0.0f; }
    if (tid < K_) inp[EH_ + tid] = 0.0f;
    __syncthreads();
    float klacc = 0.0f;
    for (int t = 0; t < T_; t++) {
        // gate = Gx[t] + Whh @ h
        {
            float a0 = 0.0f, a1 = 0.0f, a2 = 0.0f, a3 = 0.0f;
            if (t > 0) {
                const float* wt = g_WhhT + tid;
                #pragma unroll 4
                for (int i = 0; i < EH_; i += 4) {
                    a0 += wt[(i + 0) * GATE_] * hs[i + 0];
                    a1 += wt[(i + 1) * GATE_] * hs[i + 1];
                    a2 += wt[(i + 2) * GATE_] * hs[i + 2];
                    a3 += wt[(i + 3) * GATE_] * hs[i + 3];
                }
            }
            gs[tid] = g_Gx[t * GATE_ + tid] + ((a0 + a1) + (a2 + a3));
        }
        __syncthreads();
        if (tid < EH_) {
            float ig = sigmoidf_(gs[tid]);
            float fg = sigmoidf_(gs[EH_ + tid]);
            float gg = tanhf(gs[2 * EH_ + tid]);
            float og = sigmoidf_(gs[3 * EH_ + tid]);
            float c = fg * csv[tid] + ig * gg;
            csv[tid] = c;
            float h = og * tanhf(c);
            hs[tid] = h;
            inp[tid] = h;
        }
        __syncthreads();
        if (tid < K_) {
            float m = mub[tid], l = lsb[tid];
            const float* wm = g_muWT + tid;
            const float* wl = g_lsWT + tid;
            float m0 = 0, m1 = 0, l0 = 0, l1 = 0;
            #pragma unroll 2
            for (int i = 0; i < INP_; i += 2) {
                float x0 = inp[i], x1 = inp[i + 1];
                m0 += wm[i * K_] * x0;       l0 += wl[i * K_] * x0;
                m1 += wm[(i + 1) * K_] * x1; l1 += wl[(i + 1) * K_] * x1;
            }
            m += m0 + m1; l += l0 + l1;
            float pls = (t == 0) ? 0.0f : LOG_DELTA;
            float denom = expf(pls) + 1e-6f;
            float ep = inp[EH_ + tid];
            float d = m - ep;
            klk[tid] = 0.5f * ((expf(l) + d * d) / denom - 1.0f + pls - l);
            newmu[tid] = m;
            g_etas[t * K_ + tid] = m;
        }
        __syncthreads();
        if (tid < K_) inp[EH_ + tid] = newmu[tid];
        if (tid == 0) { float s = 0.0f; for (int k = 0; k < K_; k++) s += klk[k]; klacc += s; }
        __syncthreads();
    }
    if (tid == 0) g_stats[1] = klacc;
}

__global__ void build_A1_kernel(const float* __restrict__ nb, const int* __restrict__ times) {
    int idx = blockIdx.x * blockDim.x + threadIdx.x;
    if (idx >= B_ * VK_) return;
    int b = idx / VK_, j = idx % VK_;
    g_A1[idx] = (j < V_) ? nb[(size_t)b * V_ + j] : g_etas[times[b] * K_ + (j - V_)];
}

__global__ void build_alpha0_kernel(const float* __restrict__ mu) {
    int idx = blockIdx.x * blockDim.x + threadIdx.x;
    if (idx >= T_ * K_ * R_) return;
    int r = idx % R_;
    int k = (idx / R_) % K_;
    int t = idx / (R_ * K_);
    g_alpha0[idx] = mu[((size_t)k * T_ + t) * R_ + r];  // s=0 slice
}

// C[M,N] = act(A[M,Kd] * B[N,Kd]^T + bias)
template <int BM, int BN, int BK, int TM, int TN>
__global__ void sgemm_tn(const float* __restrict__ A, const float* __restrict__ Bm,
                         const float* __restrict__ bias, float* __restrict__ C,
                         int M, int N, int Kd, int act) {
    constexpr int TX = BN / TN;
    constexpr int TY = BM / TM;
    constexpr int NT = TX * TY;
    __shared__ float As[BK][BM + 1];
    __shared__ float Bs[BK][BN + 1];
    int tid = threadIdx.x;
    int tx = tid % TX, ty = tid / TX;
    int row0 = blockIdx.y * BM, col0 = blockIdx.x * BN;
    float acc[TM][TN];
    #pragma unroll
    for (int i = 0; i < TM; i++)
        #pragma unroll
        for (int j = 0; j < TN; j++) acc[i][j] = 0.0f;
    for (int k0 = 0; k0 < Kd; k0 += BK) {
        for (int i = tid; i < BM * BK; i += NT) {
            int m = i / BK, kk = i % BK;
            int gm = row0 + m, gk = k0 + kk;
            As[kk][m] = (gm < M && gk < Kd) ? A[(size_t)gm * Kd + gk] : 0.0f;
        }
        for (int i = tid; i < BN * BK; i += NT) {
            int n = i / BK, kk = i % BK;
            int gn = col0 + n, gk = k0 + kk;
            Bs[kk][n] = (gn < N && gk < Kd) ? Bm[(size_t)gn * Kd + gk] : 0.0f;
        }
        __syncthreads();
        #pragma unroll
        for (int kk = 0; kk < BK; kk++) {
            float a[TM], bb[TN];
            #pragma unroll
            for (int i = 0; i < TM; i++) a[i] = As[kk][ty * TM + i];
            #pragma unroll
            for (int j = 0; j < TN; j++) bb[j] = Bs[kk][tx * TN + j];
            #pragma unroll
            for (int i = 0; i < TM; i++)
                #pragma unroll
                for (int j = 0; j < TN; j++) acc[i][j] += a[i] * bb[j];
        }
        __syncthreads();
    }
    #pragma unroll
    for (int i = 0; i < TM; i++)
        #pragma unroll
        for (int j = 0; j < TN; j++) {
            int m = row0 + ty * TM + i, n = col0 + tx * TN + j;
            if (m < M && n < N) {
                float v = acc[i][j] + (bias ? bias[n] : 0.0f);
                if (act == 1) v = tanhf(v);
                C[(size_t)m * N + n] = v;
            }
        }
}

__global__ void softmax_beta_kernel() {
    __shared__ float red[256];
    int row = blockIdx.x, tid = threadIdx.x;
    float4* p = (float4*)(g_beta + (size_t)row * V_);
    const int n4 = V_ / 4;  // 2500
    float mx = -1e30f;
    for (int v = tid; v < n4; v += 256) {
        float4 a = p[v];
        mx = fmaxf(mx, fmaxf(fmaxf(a.x, a.y), fmaxf(a.z, a.w)));
    }
    red[tid] = mx; __syncthreads();
    for (int s = 128; s > 0; s >>= 1) { if (tid < s) red[tid] = fmaxf(red[tid], red[tid + s]); __syncthreads(); }
    mx = red[0]; __syncthreads();
    float sum = 0.0f;
    for (int v = tid; v < n4; v += 256) {
        float4 a = p[v];
        sum += expf(a.x - mx) + expf(a.y - mx) + expf(a.z - mx) + expf(a.w - mx);
    }
    red[tid] = sum; __syncthreads();
    for (int s = 128; s > 0; s >>= 1) { if (tid < s) red[tid] += red[tid + s]; __syncthreads(); }
    float inv = 1.0f / red[0];
    for (int v = tid; v < n4; v += 256) {
        float4 a = p[v];
        a.x = expf(a.x - mx) * inv;
        a.y = expf(a.y - mx) * inv;
        a.z = expf(a.z - mx) * inv;
        a.w = expf(a.w - mx) * inv;
        p[v] = a;
    }
}

__global__ void theta_kl_kernel(const int* __restrict__ times) {
    __shared__ float red[64];
    int b = blockIdx.x, tid = threadIdx.x;  // 64 threads
    float mu = (tid < K_) ? g_muth[b * K_ + tid] : -1e30f;
    red[tid] = mu; __syncthreads();
    for (int s = 32; s > 0; s >>= 1) { if (tid < s) red[tid] = fmaxf(red[tid], red[tid + s]); __syncthreads(); }
    float mx = red[0]; __syncthreads();
    float e = (tid < K_) ? expf(mu - mx) : 0.0f;
    red[tid] = e; __syncthreads();
    for (int s = 32; s > 0; s >>= 1) { if (tid < s) red[tid] += red[tid + s]; __syncthreads(); }
    float sum = red[0]; __syncthreads();
    if (tid < K_) g_theta[b * K_ + tid] = e / sum;
    float kl = 0.0f;
    if (tid < K_) {
        float ls = g_lsth[b * K_ + tid];
        float et = g_etas[times[b] * K_ + tid];
        float d = mu - et;
        kl = 0.5f * ((expf(ls) + d * d) / (1.0f + 1e-6f) - 1.0f - ls);
    }
    red[tid] = kl; __syncthreads();
    for (int s = 32; s > 0; s >>= 1) { if (tid < s) red[tid] += red[tid + s]; __syncthreads(); }
    if (tid == 0) atomicAdd(&g_stats[3], red[0]);
}

#define NLL_SPLIT 5
__global__ void nll_kernel(const float* __restrict__ bows, const int* __restrict__ times) {
    __shared__ float th[K_];
    __shared__ float sh[256];
    int b = blockIdx.x, tid = threadIdx.x;
    const int n4 = V_ / 4;                 // 2500 float4 per row
    const int c4 = n4 / NLL_SPLIT;         // 500 per split
    int v0 = blockIdx.y * c4;
    if (tid < K_) th[tid] = g_theta[b * K_ + tid];
    __syncthreads();
    int tb = times[b];
    const float* beta = g_beta + (size_t)tb * K_ * V_;
    const float4* bw4 = (const float4*)(bows + (size_t)b * V_);
    float acc = 0.0f;
    for (int v = v0 + tid; v < v0 + c4; v += 256) {
        float4 mix = make_float4(1e-6f, 1e-6f, 1e-6f, 1e-6f);
        #pragma unroll 5
        for (int k = 0; k < K_; k++) {
            float t = th[k];
            float4 bb = ((const float4*)(beta + (size_t)k * V_))[v];
            mix.x += t * bb.x; mix.y += t * bb.y; mix.z += t * bb.z; mix.w += t * bb.w;
        }
        float4 w = bw4[v];
        acc -= logf(mix.x) * w.x + logf(mix.y) * w.y + logf(mix.z) * w.z + logf(mix.w) * w.w;
    }
    float tot = blockReduceSum256(acc, sh);
    if (tid == 0) atomicAdd(&g_stats[2], tot);
}

__global__ void finalize_kernel(const int* __restrict__ num_docs, float* __restrict__ out,
                                int out_size) {
    float coeff = (float)num_docs[0] / (float)B_;
    float nll_s = g_stats[2] * coeff;
    float klth = g_stats[3] * coeff;
    float nelbo = nll_s + g_stats[0] + g_stats[1] + klth;
    if (out_size > 0) out[0] = nelbo;
    if (out_size > 1) out[1] = nll_s;
    if (out_size > 2) out[2] = g_stats[0];
    if (out_size > 3) out[3] = g_stats[1];
    if (out_size > 4) out[4] = klth;
}

// ---------------- launch ------------------------------------------------------
extern "C" void kernel_launch(void* const* d_in, const int* in_sizes, int n_in,
                              void* d_out, int out_size) {
    const float* mu_q_alpha   = (const float*)d_in[0];
    const float* lsig_q_alpha = (const float*)d_in[1];
    const float* src_logcov   = (const float*)d_in[2];
    const float* rho_W        = (const float*)d_in[3];
    const float* theta_W1     = (const float*)d_in[4];
    const float* theta_b1     = (const float*)d_in[5];
    const float* theta_W2     = (const float*)d_in[6];
    const float* theta_b2     = (const float*)d_in[7];
    const float* mu_theta_W   = (const float*)d_in[8];
    const float* mu_theta_b   = (const float*)d_in[9];
    const float* ls_theta_W   = (const float*)d_in[10];
    const float* ls_theta_b   = (const float*)d_in[11];
    const float* eta_map_W    = (const float*)d_in[12];
    const float* eta_map_b    = (const float*)d_in[13];
    const float* lstm_Wih     = (const float*)d_in[14];
    const float* lstm_Whh     = (const float*)d_in[15];
    const float* lstm_bih     = (const float*)d_in[16];
    const float* lstm_bhh     = (const float*)d_in[17];
    const float* mu_eta_W     = (const float*)d_in[18];
    const float* mu_eta_b     = (const float*)d_in[19];
    const float* ls_eta_W     = (const float*)d_in[20];
    const float* ls_eta_b     = (const float*)d_in[21];
    const float* bows         = (const float*)d_in[22];
    const float* norm_bows    = (const float*)d_in[23];
    const float* rnn_inp      = (const float*)d_in[24];
    const int*   times        = (const int*)d_in[25];
    const int*   num_docs     = (const int*)d_in[26];
    float* out = (float*)d_out;

    float *d_A1, *d_h1, *d_h2, *d_muth, *d_lsth, *d_alpha0, *d_beta, *d_xemb, *d_Gx, *d_biasc;
    cudaGetSymbolAddress((void**)&d_A1, g_A1);
    cudaGetSymbolAddress((void**)&d_h1, g_h1);
    cudaGetSymbolAddress((void**)&d_h2, g_h2);
    cudaGetSymbolAddress((void**)&d_muth, g_muth);
    cudaGetSymbolAddress((void**)&d_lsth, g_lsth);
    cudaGetSymbolAddress((void**)&d_alpha0, g_alpha0);
    cudaGetSymbolAddress((void**)&d_beta, g_beta);
    cudaGetSymbolAddress((void**)&d_xemb, g_xemb);
    cudaGetSymbolAddress((void**)&d_Gx, g_Gx);
    cudaGetSymbolAddress((void**)&d_biasc, g_biasc);

    init_kernel<<<1, 32>>>();
    prep_prior_kernel<<<1, 1>>>(src_logcov);
    {
        int n = GATE_ * EH_;
        prep_lstm_kernel<<<(n + 255) / 256, 256>>>(lstm_Whh, mu_eta_W, ls_eta_W,
                                                   lstm_bih, lstm_bhh);
    }
    {
        int n = K_ * T_ * R_;
        kl_alpha_kernel<<<(n + 255) / 256, 256>>>(mu_q_alpha, lsig_q_alpha);
    }
    {
        int warps = T_ * EH_;
        xemb_kernel<<<(warps * 32 + 255) / 256, 256>>>(rnn_inp, eta_map_W, eta_map_b);
    }
    // Gx[t][gate] = xemb[t] @ Wih^T + (bih + bhh)  : (25 x 200) x (800 x 200)^T
    {
        dim3 grid((GATE_ + 31) / 32, (T_ + 31) / 32);
        sgemm_tn<32, 32, 32, 2, 2><<<grid, 256>>>(d_xemb, lstm_Wih, d_biasc, d_Gx,
                                                  T_, GATE_, EH_, 0);
    }
    lstm_eta_kernel<<<1, GATE_>>>(mu_eta_b, ls_eta_b);
    {
        int n = B_ * VK_;
        build_A1_kernel<<<(n + 255) / 256, 256>>>(norm_bows, times);
    }
    // h1 = tanh(A1 @ W1^T + b1)  : (128 x 10050) x (800 x 10050)^T
    {
        dim3 grid((TH_ + 31) / 32, (B_ + 31) / 32);
        sgemm_tn<32, 32, 32, 2, 2><<<grid, 256>>>(d_A1, theta_W1, theta_b1, d_h1,
                                                  B_, TH_, VK_, 1);
    }
    // h2 = tanh(h1 @ W2^T + b2)
    {
        dim3 grid((TH_ + 31) / 32, (B_ + 31) / 32);
        sgemm_tn<32, 32, 32, 2, 2><<<grid, 256>>>(d_h1, theta_W2, theta_b2, d_h2,
                                                  B_, TH_, TH_, 1);
    }
    // mu_th / ls_th
    {
        dim3 grid((K_ + 31) / 32, (B_ + 31) / 32);
        sgemm_tn<32, 32, 32, 2, 2><<<grid, 256>>>(d_h2, mu_theta_W, mu_theta_b, d_muth,
                                                  B_, K_, TH_, 0);
        sgemm_tn<32, 32, 32, 2, 2><<<grid, 256>>>(d_h2, ls_theta_W, ls_theta_b, d_lsth,
                                                  B_, K_, TH_, 0);
    }
    {
        int n = T_ * K_ * R_;
        build_alpha0_kernel<<<(n + 255) / 256, 256>>>(mu_q_alpha);
    }
    // beta logits: (1250 x 128) x (10000 x 128)^T
    {
        dim3 grid((V_ + 63) / 64, (T_ * K_ + 63) / 64);
        sgemm_tn<64, 64, 16, 4, 4><<<grid, 256>>>(d_alpha0, rho_W, nullptr, d_beta,
                                                  T_ * K_, V_, R_, 0);
    }
    softmax_beta_kernel<<<T_ * K_, 256>>>();
    theta_kl_kernel<<<B_, 64>>>(times);
    {
        dim3 grid(B_, NLL_SPLIT);
        nll_kernel<<<grid, 256>>>(bows, times);
    }
    finalize_kernel<<<1, 1>>>(num_docs, out, out_size);
}

// round 6
// speedup vs baseline: 2.5020x; 1.1110x over previous
#include <cuda_runtime.h>
#include <math.h>
#include <stdint.h>

#define S_ 4
#define K_ 50
#define T_ 25
#define R_ 128
#define V_ 10000
#define TH_ 800
#define EH_ 200
#define B_ 128
#define VK_ (V_ + K_)
#define GATE_ (4 * EH_)    /* 800 */
#define INP_  (EH_ + K_)   /* 250 */
#define INP4_ 64           /* padded input quads: 64*4 = 256 >= 250 */
#define EH4_  (EH_ / 4)    /* 50 */
#define LOG_DELTA (-5.2983173665480363f) /* log(0.005) */

// ---------------- scratch (static device globals; no allocation) -------------
__device__ float g_xemb[T_ * EH_];
__device__ float g_etas[T_ * K_];
__device__ float g_A1[B_ * VK_];
__device__ float g_h1[B_ * TH_];
__device__ float g_h2[B_ * TH_];
__device__ float g_muth[B_ * K_];
__device__ float g_lsth[B_ * K_];
__device__ float g_theta[B_ * K_];
__device__ float g_alpha0[T_ * K_ * R_];
__device__ float g_beta[(size_t)T_ * K_ * V_];   // 12.5M floats = 50 MB
// LSTM prep scratch (float4-packed, transposed for coalesced + high-MLP reads)
__device__ float4 g_WhhT4[EH4_ * GATE_];   // [50][800]: quad of input-dims i per gate o
__device__ float4 g_muWT4[INP4_ * K_];     // [64][50], zero-padded i
__device__ float4 g_lsWT4[INP4_ * K_];
__device__ float g_biasc[GATE_];
__device__ float g_Gx[T_ * GATE_];         // x-part of gates, all t
// stats: 0=kl_alpha 1=kl_eta 2=nll_raw 3=klth_raw 4=ld_p0 5..8=d_p0 9=ld_pt 10..13=d_pt
__device__ float g_stats[16];

// ---------------- helpers ----------------------------------------------------
__device__ __forceinline__ float sigmoidf_(float x) { return 1.0f / (1.0f + expf(-x)); }

__device__ __forceinline__ float blockReduceSum256(float v, float* sh) {
    int tid = threadIdx.x;
    sh[tid] = v;
    __syncthreads();
    for (int s = blockDim.x >> 1; s > 0; s >>= 1) {
        if (tid < s) sh[tid] += sh[tid + s];
        __syncthreads();
    }
    return sh[0];
}

__device__ double logabsdet4(double M[4][4]) {
    double ld = 0.0;
    for (int i = 0; i < 4; i++) {
        int p = i; double best = fabs(M[i][i]);
        for (int r = i + 1; r < 4; r++)
            if (fabs(M[r][i]) > best) { best = fabs(M[r][i]); p = r; }
        if (p != i)
            for (int c = 0; c < 4; c++) { double t = M[i][c]; M[i][c] = M[p][c]; M[p][c] = t; }
        ld += log(fabs(M[i][i]));
        for (int r = i + 1; r < 4; r++) {
            double f = M[r][i] / M[i][i];
            for (int c = i; c < 4; c++) M[r][c] -= f * M[i][c];
        }
    }
    return ld;
}

// ---------------- kernels ----------------------------------------------------
__global__ void init_kernel() {
    int t = threadIdx.x;
    if (t == 0 || t == 2 || t == 3) g_stats[t] = 0.0f;  // atomic accumulators only
}

__global__ void prep_prior_kernel(const float* __restrict__ src) {
    double M0[4][4], Mt[4][4];
    for (int i = 0; i < 4; i++)
        for (int j = 0; j < 4; j++) {
            double v = (double)src[i * 4 + j];
            M0[i][j] = exp(v);
            Mt[i][j] = 0.005 * v;
        }
    for (int i = 0; i < 4; i++) {
        g_stats[5 + i]  = (float)M0[i][i];
        g_stats[10 + i] = (float)Mt[i][i];
    }
    g_stats[4] = (float)logabsdet4(M0);
    g_stats[9] = (float)logabsdet4(Mt);
}

// pack LSTM/eta weights as transposed float4 quads + combined bias
__global__ void prep_lstm_kernel(const float* __restrict__ Whh,
                                 const float* __restrict__ muW, const float* __restrict__ lsW,
                                 const float* __restrict__ bih, const float* __restrict__ bhh) {
    int idx = blockIdx.x * blockDim.x + threadIdx.x;
    if (idx < EH4_ * GATE_) {
        int i4 = idx / GATE_, o = idx % GATE_;
        const float* w = Whh + (size_t)o * EH_ + 4 * i4;
        g_WhhT4[idx] = make_float4(w[0], w[1], w[2], w[3]);
    }
    if (idx < INP4_ * K_) {
        int i4 = idx / K_, k = idx % K_;
        float4 m, l;
        float* mp = (float*)&m;
        float* lp = (float*)&l;
        for (int j = 0; j < 4; j++) {
            int i = 4 * i4 + j;
            mp[j] = (i < INP_) ? muW[(size_t)k * INP_ + i] : 0.0f;
            lp[j] = (i < INP_) ? lsW[(size_t)k * INP_ + i] : 0.0f;
        }
        g_muWT4[idx] = m;
        g_lsWT4[idx] = l;
    }
    if (idx < GATE_) g_biasc[idx] = bih[idx] + bhh[idx];
}

__global__ void kl_alpha_kernel(const float* __restrict__ mu, const float* __restrict__ lsig) {
    __shared__ float sh[256];
    int idx = blockIdx.x * blockDim.x + threadIdx.x;
    float val = 0.0f;
    if (idx < K_ * T_ * R_) {
        int r = idx % R_;
        int t = (idx / R_) % T_;
        int k = idx / (R_ * T_);
        float ldp = (t == 0) ? g_stats[4] : g_stats[9];
        const float* dp = (t == 0) ? &g_stats[5] : &g_stats[10];
        float acc = -ldp - (float)S_;
        for (int s = 0; s < S_; s++) {
            size_t off = ((size_t)(s * K_ + k) * T_ + t) * R_ + r;
            float lsv = lsig[off];
            float invq = expf(-lsv);
            float m = mu[off];
            float dmu = (t == 0) ? m : (m - mu[off - R_]);
            acc += lsv + dp[s] * invq + dmu * dmu * invq;
        }
        val = acc;
    }
    float tot = blockReduceSum256(val, sh);
    if (threadIdx.x == 0) atomicAdd(&g_stats[0], tot);
}

// x_emb[t][e] = rnn_inp[t] . eta_map_W[e] + b[e]   (warp per output, float4)
__global__ void xemb_kernel(const float* __restrict__ rnn, const float* __restrict__ W,
                            const float* __restrict__ b) {
    int gw = (blockIdx.x * blockDim.x + threadIdx.x) >> 5;
    int lane = threadIdx.x & 31;
    if (gw >= T_ * EH_) return;
    int t = gw / EH_, e = gw % EH_;
    const float4* x = (const float4*)(rnn + (size_t)t * V_);
    const float4* w = (const float4*)(W + (size_t)e * V_);
    float acc = 0.0f;
    for (int v = lane; v < V_ / 4; v += 32) {
        float4 a = x[v], c = w[v];
        acc += a.x * c.x + a.y * c.y + a.z * c.z + a.w * c.w;
    }
    for (int o = 16; o > 0; o >>= 1) acc += __shfl_down_sync(0xffffffffu, acc, o);
    if (lane == 0) g_xemb[t * EH_ + e] = acc + b[e];
}

// sequential LSTM recurrence + eta Markov scan; x-part of gates precomputed (g_Gx).
// float4-packed transposed weights + deep unroll -> high MLP, latency-tolerant.
__global__ void lstm_eta_kernel(const float* __restrict__ mub, const float* __restrict__ lsb) {
    __shared__ float hs[EH_], gs[GATE_], csv[EH_];
    __shared__ float inp[4 * INP4_];   // [0..199]=h, [200..249]=eta_prev, [250..255]=0
    __shared__ float newmu[K_], klk[K_];
    int tid = threadIdx.x;
    if (tid < EH_) { hs[tid] = 0.0f; csv[tid] = 0.0f; }
    if (tid < 4 * INP4_) inp[tid] = 0.0f;
    __syncthreads();
    float klacc = 0.0f;
    for (int t = 0; t < T_; t++) {
        // gate = Gx[t] + Whh @ h
        {
            float a0 = 0.0f, a1 = 0.0f, a2 = 0.0f, a3 = 0.0f;
            if (t > 0) {
                const float4* wt = g_WhhT4 + tid;
                #pragma unroll 10
                for (int i4 = 0; i4 < EH4_; i4++) {
                    float4 w = wt[i4 * GATE_];
                    a0 += w.x * hs[4 * i4 + 0];
                    a1 += w.y * hs[4 * i4 + 1];
                    a2 += w.z * hs[4 * i4 + 2];
                    a3 += w.w * hs[4 * i4 + 3];
                }
            }
            gs[tid] = g_Gx[t * GATE_ + tid] + ((a0 + a1) + (a2 + a3));
        }
        __syncthreads();
        if (tid < EH_) {
            float ig = sigmoidf_(gs[tid]);
            float fg = sigmoidf_(gs[EH_ + tid]);
            float gg = tanhf(gs[2 * EH_ + tid]);
            float og = sigmoidf_(gs[3 * EH_ + tid]);
            float c = fg * csv[tid] + ig * gg;
            csv[tid] = c;
            float h = og * tanhf(c);
            hs[tid] = h;
            inp[tid] = h;
        }
        __syncthreads();
        if (tid < K_) {
            float m0 = 0, m1 = 0, l0 = 0, l1 = 0;
            const float4* wm = g_muWT4 + tid;
            const float4* wl = g_lsWT4 + tid;
            #pragma unroll 8
            for (int i4 = 0; i4 < INP4_; i4++) {
                float4 a = wm[i4 * K_];
                float4 bq = wl[i4 * K_];
                float x0 = inp[4 * i4 + 0], x1 = inp[4 * i4 + 1];
                float x2 = inp[4 * i4 + 2], x3 = inp[4 * i4 + 3];
                m0 += a.x * x0 + a.y * x1;
                m1 += a.z * x2 + a.w * x3;
                l0 += bq.x * x0 + bq.y * x1;
                l1 += bq.z * x2 + bq.w * x3;
            }
            float m = mub[tid] + m0 + m1;
            float l = lsb[tid] + l0 + l1;
            float pls = (t == 0) ? 0.0f : LOG_DELTA;
            float denom = expf(pls) + 1e-6f;
            float ep = inp[EH_ + tid];
            float d = m - ep;
            klk[tid] = 0.5f * ((expf(l) + d * d) / denom - 1.0f + pls - l);
            newmu[tid] = m;
            g_etas[t * K_ + tid] = m;
        }
        __syncthreads();
        if (tid < K_) inp[EH_ + tid] = newmu[tid];
        if (tid == 0) { float s = 0.0f; for (int k = 0; k < K_; k++) s += klk[k]; klacc += s; }
        __syncthreads();
    }
    if (tid == 0) g_stats[1] = klacc;
}

__global__ void build_A1_kernel(const float* __restrict__ nb, const int* __restrict__ times) {
    int idx = blockIdx.x * blockDim.x + threadIdx.x;
    if (idx >= B_ * VK_) return;
    int b = idx / VK_, j = idx % VK_;
    g_A1[idx] = (j < V_) ? nb[(size_t)b * V_ + j] : g_etas[times[b] * K_ + (j - V_)];
}

__global__ void build_alpha0_kernel(const float* __restrict__ mu) {
    int idx = blockIdx.x * blockDim.x + threadIdx.x;
    if (idx >= T_ * K_ * R_) return;
    int r = idx % R_;
    int k = (idx / R_) % K_;
    int t = idx / (R_ * K_);
    g_alpha0[idx] = mu[((size_t)k * T_ + t) * R_ + r];  // s=0 slice
}

// C[M,N] = act(A[M,Kd] * B[N,Kd]^T + bias)
template <int BM, int BN, int BK, int TM, int TN>
__global__ void sgemm_tn(const float* __restrict__ A, const float* __restrict__ Bm,
                         const float* __restrict__ bias, float* __restrict__ C,
                         int M, int N, int Kd, int act) {
    constexpr int TX = BN / TN;
    constexpr int TY = BM / TM;
    constexpr int NT = TX * TY;
    __shared__ float As[BK][BM + 1];
    __shared__ float Bs[BK][BN + 1];
    int tid = threadIdx.x;
    int tx = tid % TX, ty = tid / TX;
    int row0 = blockIdx.y * BM, col0 = blockIdx.x * BN;
    float acc[TM][TN];
    #pragma unroll
    for (int i = 0; i < TM; i++)
        #pragma unroll
        for (int j = 0; j < TN; j++) acc[i][j] = 0.0f;
    for (int k0 = 0; k0 < Kd; k0 += BK) {
        for (int i = tid; i < BM * BK; i += NT) {
            int m = i / BK, kk = i % BK;
            int gm = row0 + m, gk = k0 + kk;
            As[kk][m] = (gm < M && gk < Kd) ? A[(size_t)gm * Kd + gk] : 0.0f;
        }
        for (int i = tid; i < BN * BK; i += NT) {
            int n = i / BK, kk = i % BK;
            int gn = col0 + n, gk = k0 + kk;
            Bs[kk][n] = (gn < N && gk < Kd) ? Bm[(size_t)gn * Kd + gk] : 0.0f;
        }
        __syncthreads();
        #pragma unroll
        for (int kk = 0; kk < BK; kk++) {
            float a[TM], bb[TN];
            #pragma unroll
            for (int i = 0; i < TM; i++) a[i] = As[kk][ty * TM + i];
            #pragma unroll
            for (int j = 0; j < TN; j++) bb[j] = Bs[kk][tx * TN + j];
            #pragma unroll
            for (int i = 0; i < TM; i++)
                #pragma unroll
                for (int j = 0; j < TN; j++) acc[i][j] += a[i] * bb[j];
        }
        __syncthreads();
    }
    #pragma unroll
    for (int i = 0; i < TM; i++)
        #pragma unroll
        for (int j = 0; j < TN; j++) {
            int m = row0 + ty * TM + i, n = col0 + tx * TN + j;
            if (m < M && n < N) {
                float v = acc[i][j] + (bias ? bias[n] : 0.0f);
                if (act == 1) v = tanhf(v);
                C[(size_t)m * N + n] = v;
            }
        }
}

__global__ void softmax_beta_kernel() {
    __shared__ float red[256];
    int row = blockIdx.x, tid = threadIdx.x;
    float4* p = (float4*)(g_beta + (size_t)row * V_);
    const int n4 = V_ / 4;  // 2500
    float mx = -1e30f;
    for (int v = tid; v < n4; v += 256) {
        float4 a = p[v];
        mx = fmaxf(mx, fmaxf(fmaxf(a.x, a.y), fmaxf(a.z, a.w)));
    }
    red[tid] = mx; __syncthreads();
    for (int s = 128; s > 0; s >>= 1) { if (tid < s) red[tid] = fmaxf(red[tid], red[tid + s]); __syncthreads(); }
    mx = red[0]; __syncthreads();
    float sum = 0.0f;
    for (int v = tid; v < n4; v += 256) {
        float4 a = p[v];
        sum += expf(a.x - mx) + expf(a.y - mx) + expf(a.z - mx) + expf(a.w - mx);
    }
    red[tid] = sum; __syncthreads();
    for (int s = 128; s > 0; s >>= 1) { if (tid < s) red[tid] += red[tid + s]; __syncthreads(); }
    float inv = 1.0f / red[0];
    for (int v = tid; v < n4; v += 256) {
        float4 a = p[v];
        a.x = expf(a.x - mx) * inv;
        a.y = expf(a.y - mx) * inv;
        a.z = expf(a.z - mx) * inv;
        a.w = expf(a.w - mx) * inv;
        p[v] = a;
    }
}

__global__ void theta_kl_kernel(const int* __restrict__ times) {
    __shared__ float red[64];
    int b = blockIdx.x, tid = threadIdx.x;  // 64 threads
    float mu = (tid < K_) ? g_muth[b * K_ + tid] : -1e30f;
    red[tid] = mu; __syncthreads();
    for (int s = 32; s > 0; s >>= 1) { if (tid < s) red[tid] = fmaxf(red[tid], red[tid + s]); __syncthreads(); }
    float mx = red[0]; __syncthreads();
    float e = (tid < K_) ? expf(mu - mx) : 0.0f;
    red[tid] = e; __syncthreads();
    for (int s = 32; s > 0; s >>= 1) { if (tid < s) red[tid] += red[tid + s]; __syncthreads(); }
    float sum = red[0]; __syncthreads();
    if (tid < K_) g_theta[b * K_ + tid] = e / sum;
    float kl = 0.0f;
    if (tid < K_) {
        float ls = g_lsth[b * K_ + tid];
        float et = g_etas[times[b] * K_ + tid];
        float d = mu - et;
        kl = 0.5f * ((expf(ls) + d * d) / (1.0f + 1e-6f) - 1.0f - ls);
    }
    red[tid] = kl; __syncthreads();
    for (int s = 32; s > 0; s >>= 1) { if (tid < s) red[tid] += red[tid + s]; __syncthreads(); }
    if (tid == 0) atomicAdd(&g_stats[3], red[0]);
}

#define NLL_SPLIT 5
__global__ void nll_kernel(const float* __restrict__ bows, const int* __restrict__ times) {
    __shared__ float th[K_];
    __shared__ float sh[256];
    int b = blockIdx.x, tid = threadIdx.x;
    const int n4 = V_ / 4;                 // 2500 float4 per row
    const int c4 = n4 / NLL_SPLIT;         // 500 per split
    int v0 = blockIdx.y * c4;
    if (tid < K_) th[tid] = g_theta[b * K_ + tid];
    __syncthreads();
    int tb = times[b];
    const float* beta = g_beta + (size_t)tb * K_ * V_;
    const float4* bw4 = (const float4*)(bows + (size_t)b * V_);
    float acc = 0.0f;
    for (int v = v0 + tid; v < v0 + c4; v += 256) {
        float4 mix = make_float4(1e-6f, 1e-6f, 1e-6f, 1e-6f);
        #pragma unroll 5
        for (int k = 0; k < K_; k++) {
            float t = th[k];
            float4 bb = ((const float4*)(beta + (size_t)k * V_))[v];
            mix.x += t * bb.x; mix.y += t * bb.y; mix.z += t * bb.z; mix.w += t * bb.w;
        }
        float4 w = bw4[v];
        acc -= logf(mix.x) * w.x + logf(mix.y) * w.y + logf(mix.z) * w.z + logf(mix.w) * w.w;
    }
    float tot = blockReduceSum256(acc, sh);
    if (tid == 0) atomicAdd(&g_stats[2], tot);
}

__global__ void finalize_kernel(const int* __restrict__ num_docs, float* __restrict__ out,
                                int out_size) {
    float coeff = (float)num_docs[0] / (float)B_;
    float nll_s = g_stats[2] * coeff;
    float klth = g_stats[3] * coeff;
    float nelbo = nll_s + g_stats[0] + g_stats[1] + klth;
    if (out_size > 0) out[0] = nelbo;
    if (out_size > 1) out[1] = nll_s;
    if (out_size > 2) out[2] = g_stats[0];
    if (out_size > 3) out[3] = g_stats[1];
    if (out_size > 4) out[4] = klth;
}

// ---------------- launch ------------------------------------------------------
extern "C" void kernel_launch(void* const* d_in, const int* in_sizes, int n_in,
                              void* d_out, int out_size) {
    const float* mu_q_alpha   = (const float*)d_in[0];
    const float* lsig_q_alpha = (const float*)d_in[1];
    const float* src_logcov   = (const float*)d_in[2];
    const float* rho_W        = (const float*)d_in[3];
    const float* theta_W1     = (const float*)d_in[4];
    const float* theta_b1     = (const float*)d_in[5];
    const float* theta_W2     = (const float*)d_in[6];
    const float* theta_b2     = (const float*)d_in[7];
    const float* mu_theta_W   = (const float*)d_in[8];
    const float* mu_theta_b   = (const float*)d_in[9];
    const float* ls_theta_W   = (const float*)d_in[10];
    const float* ls_theta_b   = (const float*)d_in[11];
    const float* eta_map_W    = (const float*)d_in[12];
    const float* eta_map_b    = (const float*)d_in[13];
    const float* lstm_Wih     = (const float*)d_in[14];
    const float* lstm_Whh     = (const float*)d_in[15];
    const float* lstm_bih     = (const float*)d_in[16];
    const float* lstm_bhh     = (const float*)d_in[17];
    const float* mu_eta_W     = (const float*)d_in[18];
    const float* mu_eta_b     = (const float*)d_in[19];
    const float* ls_eta_W     = (const float*)d_in[20];
    const float* ls_eta_b     = (const float*)d_in[21];
    const float* bows         = (const float*)d_in[22];
    const float* norm_bows    = (const float*)d_in[23];
    const float* rnn_inp      = (const float*)d_in[24];
    const int*   times        = (const int*)d_in[25];
    const int*   num_docs     = (const int*)d_in[26];
    float* out = (float*)d_out;

    float *d_A1, *d_h1, *d_h2, *d_muth, *d_lsth, *d_alpha0, *d_beta, *d_xemb, *d_Gx, *d_biasc;
    cudaGetSymbolAddress((void**)&d_A1, g_A1);
    cudaGetSymbolAddress((void**)&d_h1, g_h1);
    cudaGetSymbolAddress((void**)&d_h2, g_h2);
    cudaGetSymbolAddress((void**)&d_muth, g_muth);
    cudaGetSymbolAddress((void**)&d_lsth, g_lsth);
    cudaGetSymbolAddress((void**)&d_alpha0, g_alpha0);
    cudaGetSymbolAddress((void**)&d_beta, g_beta);
    cudaGetSymbolAddress((void**)&d_xemb, g_xemb);
    cudaGetSymbolAddress((void**)&d_Gx, g_Gx);
    cudaGetSymbolAddress((void**)&d_biasc, g_biasc);

    // R3-proven launch order; float4-packed scan weights are the only change.
    init_kernel<<<1, 32>>>();
    prep_prior_kernel<<<1, 1>>>(src_logcov);
    {
        int n = EH4_ * GATE_;  // 40000, covers all prep work
        prep_lstm_kernel<<<(n + 255) / 256, 256>>>(lstm_Whh, mu_eta_W, ls_eta_W,
                                                   lstm_bih, lstm_bhh);
    }
    {
        int n = K_ * T_ * R_;
        kl_alpha_kernel<<<(n + 255) / 256, 256>>>(mu_q_alpha, lsig_q_alpha);
    }
    {
        int warps = T_ * EH_;
        xemb_kernel<<<(warps * 32 + 255) / 256, 256>>>(rnn_inp, eta_map_W, eta_map_b);
    }
    // Gx[t][gate] = xemb[t] @ Wih^T + (bih + bhh)
    {
        dim3 grid((GATE_ + 31) / 32, (T_ + 31) / 32);
        sgemm_tn<32, 32, 32, 2, 2><<<grid, 256>>>(d_xemb, lstm_Wih, d_biasc, d_Gx,
                                                  T_, GATE_, EH_, 0);
    }
    lstm_eta_kernel<<<1, GATE_>>>(mu_eta_b, ls_eta_b);
    {
        int n = B_ * VK_;
        build_A1_kernel<<<(n + 255) / 256, 256>>>(norm_bows, times);
    }
    // h1 = tanh(A1 @ W1^T + b1)  : (128 x 10050) x (800 x 10050)^T
    {
        dim3 grid((TH_ + 31) / 32, (B_ + 31) / 32);
        sgemm_tn<32, 32, 32, 2, 2><<<grid, 256>>>(d_A1, theta_W1, theta_b1, d_h1,
                                                  B_, TH_, VK_, 1);
    }
    // h2 = tanh(h1 @ W2^T + b2)
    {
        dim3 grid((TH_ + 31) / 32, (B_ + 31) / 32);
        sgemm_tn<32, 32, 32, 2, 2><<<grid, 256>>>(d_h1, theta_W2, theta_b2, d_h2,
                                                  B_, TH_, TH_, 1);
    }
    // mu_th / ls_th
    {
        dim3 grid((K_ + 31) / 32, (B_ + 31) / 32);
        sgemm_tn<32, 32, 32, 2, 2><<<grid, 256>>>(d_h2, mu_theta_W, mu_theta_b, d_muth,
                                                  B_, K_, TH_, 0);
        sgemm_tn<32, 32, 32, 2, 2><<<grid, 256>>>(d_h2, ls_theta_W, ls_theta_b, d_lsth,
                                                  B_, K_, TH_, 0);
    }
    {
        int n = T_ * K_ * R_;
        build_alpha0_kernel<<<(n + 255) / 256, 256>>>(mu_q_alpha);
    }
    // beta logits: (1250 x 128) x (10000 x 128)^T
    {
        dim3 grid((V_ + 63) / 64, (T_ * K_ + 63) / 64);
        sgemm_tn<64, 64, 16, 4, 4><<<grid, 256>>>(d_alpha0, rho_W, nullptr, d_beta,
                                                  T_ * K_, V_, R_, 0);
    }
    softmax_beta_kernel<<<T_ * K_, 256>>>();
    theta_kl_kernel<<<B_, 64>>>(times);
    {
        dim3 grid(B_, NLL_SPLIT);
        nll_kernel<<<grid, 256>>>(bows, times);
    }
    finalize_kernel<<<1, 1>>>(num_docs, out, out_size);
}